// round 1
// baseline (speedup 1.0000x reference)
#include <cuda_runtime.h>
#include <cuda_bf16.h>
#include <math.h>

// Problem constants
#define C0 64          // in channels
#define T  512         // time (after swap)
#define F  256         // freq (after swap) == N samples for SRU/conv
#define LL 506         // conv-window count L
#define KW 7
#define HH 32          // SRU hidden
#define C2 128
#define M_ROWS (F*LL)          // 129536 (divisible by 64)
#define U_STRIDE (M_ROWS*128)  // 16580608
#define EPSV 1e-6f

// ---------------- scratch (device globals; no allocs allowed) ----------------
__device__ float  g_X2 [T*F*C0];        // gn0-normalized x, layout [t][f][c]
__device__ float  g_U  [2*M_ROWS*128];  // SRU gates, [d][l*256+n][128]
__device__ float  g_y  [M_ROWS*C0];     // SRU output = s2, [n][l][c]
__device__ float  g_a1 [M_ROWS*C2];
__device__ float  g_a2 [M_ROWS*C2];
__device__ float  g_a3r[M_ROWS*C0];
__device__ float  g_a3 [M_ROWS*C0];
__device__ double g_part[1024];         // 512 blocks x (sum, sumsq)
__device__ float  g_stats0[2];          // gn0 mean, rstd
__device__ float  g_stats[3][F*2];      // gn1/gn2/gn3 per-sample mean, rstd
__device__ float  g_w1t[C0*C2];         // c1_w  -> [c][o]
__device__ float  g_w2t[KW*C2*C2];      // c2_w  -> [k][c][o]
__device__ float  g_w3t[C2*C0];         // c3_w  -> [c][o]
__device__ float  g_wct[KW*C0*C0];      // ct_w  -> [j][c][o]

__device__ __forceinline__ float sigf(float v){ return 1.f/(1.f+__expf(-v)); }

// ---------------- gn0: global mean/var over whole input ----------------
__global__ void k_red0(const float* __restrict__ x){
    double s=0.0, q=0.0;
    for(int i = blockIdx.x*256 + threadIdx.x; i < T*F*C0; i += 512*256){
        double v = x[i]; s += v; q += v*v;
    }
    __shared__ double shs[256], shq[256];
    int tid = threadIdx.x;
    shs[tid]=s; shq[tid]=q; __syncthreads();
    for(int o=128;o>0;o>>=1){ if(tid<o){shs[tid]+=shs[tid+o]; shq[tid]+=shq[tid+o];} __syncthreads(); }
    if(tid==0){ g_part[blockIdx.x*2]=shs[0]; g_part[blockIdx.x*2+1]=shq[0]; }
}
__global__ void k_red0b(){
    double s=0.0, q=0.0;
    int tid = threadIdx.x;
    for(int b=tid;b<512;b+=256){ s += g_part[2*b]; q += g_part[2*b+1]; }
    __shared__ double shs[256], shq[256];
    shs[tid]=s; shq[tid]=q; __syncthreads();
    for(int o=128;o>0;o>>=1){ if(tid<o){shs[tid]+=shs[tid+o]; shq[tid]+=shq[tid+o];} __syncthreads(); }
    if(tid==0){
        double n = (double)T*F*C0;
        double m = shs[0]/n;
        double v = shq[0]/n - m*m;
        g_stats0[0] = (float)m;
        g_stats0[1] = rsqrtf((float)v + EPSV);
    }
}

// ---------------- weight pre-transposes ----------------
__global__ void k_prep(const float* __restrict__ w1, const float* __restrict__ w2,
                       const float* __restrict__ w3, const float* __restrict__ wc){
    int i = blockIdx.x*blockDim.x + threadIdx.x;
    if(i < 8192){ int c=i/128, o=i%128; g_w1t[c*128+o] = w1[o*64+c]; return; }
    i -= 8192;
    if(i < 114688){ int o=i%128; int t=i/128; int c=t%128; int k=t/128;
                    g_w2t[(k*128+c)*128+o] = w2[o*896 + c*7 + k]; return; }
    i -= 114688;
    if(i < 8192){ int o=i%64; int c=i/64; g_w3t[c*64+o] = w3[o*128+c]; return; }
    i -= 8192;
    if(i < 28672){ int o=i%64; int t=i/64; int c=t%64; int j=t/64;
                   g_wct[(j*64+c)*64+o] = wc[c*448 + o*7 + j]; }
}

// ---------------- gn0 apply + transpose into [t][f][c] ----------------
__global__ void k_xn(const float* __restrict__ x, const float* __restrict__ w, const float* __restrict__ b){
    __shared__ float sm[32*65];
    int t0 = blockIdx.x*32;
    int f  = blockIdx.y;
    int tid = threadIdx.x;
    float mean = g_stats0[0], rstd = g_stats0[1];
    #pragma unroll
    for(int rep=0;rep<8;rep++){
        int lin = tid + rep*256;
        int c = lin >> 5, tl = lin & 31;
        float v = x[((size_t)c*F + f)*T + t0 + tl];
        v = (v-mean)*rstd*w[c] + b[c];
        sm[tl*65 + c] = v;
    }
    __syncthreads();
    #pragma unroll
    for(int rep=0;rep<8;rep++){
        int lin = tid + rep*256;
        int c = lin & 63, tl = lin >> 6;
        g_X2[((size_t)(t0+tl)*F + f)*C0 + c] = sm[tl*65 + c];
    }
}

// ---------------- SRU input GEMM: U[d,l,n,o] ----------------
// A[(l,n)][(c,k)] = X2[l+k][n][c];  B[(c,k)][(d,oo)] = sru_w[d][(c*7+k)][oo]
__global__ void k_gemm_sru(const float* __restrict__ sruw){
    __shared__ float As[16][65];
    __shared__ float Bs[16][65];
    int row0 = blockIdx.x*64;
    int col0 = blockIdx.y*64;
    int tid = threadIdx.x;
    int tx = tid & 15, ty = tid >> 4;
    float acc[4][4] = {};
    for(int k7=0;k7<7;k7++){
        for(int c0=0;c0<64;c0+=16){
            #pragma unroll
            for(int rep=0;rep<4;rep++){
                int lin = tid + rep*256;
                int kk = lin & 15, m = lin >> 4;
                As[kk][m] = g_X2[(size_t)(row0 + m + k7*256)*64 + c0 + kk];
            }
            #pragma unroll
            for(int rep=0;rep<4;rep++){
                int lin = tid + rep*256;
                int nn = lin & 63, kk = lin >> 6;
                int o = col0 + nn; int d = o >> 7; int oo = o & 127;
                Bs[kk][nn] = sruw[d*57344 + ((c0+kk)*7 + k7)*128 + oo];
            }
            __syncthreads();
            #pragma unroll
            for(int kk=0;kk<16;kk++){
                float a[4], b[4];
                #pragma unroll
                for(int i=0;i<4;i++) a[i] = As[kk][ty*4+i];
                #pragma unroll
                for(int j=0;j<4;j++) b[j] = Bs[kk][tx*4+j];
                #pragma unroll
                for(int i=0;i<4;i++)
                    #pragma unroll
                    for(int j=0;j<4;j++) acc[i][j] += a[i]*b[j];
            }
            __syncthreads();
        }
    }
    #pragma unroll
    for(int i=0;i<4;i++){
        int r = row0 + ty*4 + i;
        #pragma unroll
        for(int j=0;j<4;j++){
            int o = col0 + tx*4 + j; int d = o >> 7; int oo = o & 127;
            g_U[(size_t)d*U_STRIDE + (size_t)r*128 + oo] = acc[i][j];
        }
    }
}

// ---------------- SRU scan: one warp per (direction, n) ----------------
__global__ void k_scan(const float* __restrict__ sruv, const float* __restrict__ srub){
    int w = (blockIdx.x*blockDim.x + threadIdx.x) >> 5;   // 0..511
    int h = threadIdx.x & 31;
    int d = w >> 8; int n = w & 255;
    float vf = sruv[d*64 + h];
    float vr = sruv[d*64 + 32 + h];
    float bf = srub[d*64 + h];
    float br = srub[d*64 + 32 + h];
    float st = 0.f;
    const float* Ubase = g_U + (size_t)d*U_STRIDE + (size_t)n*128;
    for(int s=0;s<LL;s++){
        int l = d ? (LL-1-s) : s;
        const float* u = Ubase + (size_t)l*(256*128);
        float u0=u[h], u1=u[32+h], u2=u[64+h], u3=u[96+h];
        float f  = sigf(u1 + vf*st + bf);
        float cn = f*st + (1.f-f)*u0;
        float rr = sigf(u2 + vr*st + br);   // uses old state (matches reference)
        float hv = rr*cn + (1.f-rr)*u3;
        st = cn;
        g_y[((size_t)n*LL + l)*64 + d*32 + h] = hv;
    }
}

// ---------------- c1: 1x1, 64 -> 128 ----------------
__global__ void k_gemm_c1(const float* __restrict__ bias){
    __shared__ float As[16][65];
    __shared__ float Bs[16][65];
    int row0 = blockIdx.x*64;
    int col0 = blockIdx.y*64;
    int tid = threadIdx.x;
    int tx = tid & 15, ty = tid >> 4;
    float acc[4][4] = {};
    for(int c0=0;c0<64;c0+=16){
        #pragma unroll
        for(int rep=0;rep<4;rep++){
            int lin = tid + rep*256;
            int kk = lin & 15, m = lin >> 4;
            As[kk][m] = g_y[(size_t)(row0+m)*64 + c0 + kk];
        }
        #pragma unroll
        for(int rep=0;rep<4;rep++){
            int lin = tid + rep*256;
            int nn = lin & 63, kk = lin >> 6;
            Bs[kk][nn] = g_w1t[(c0+kk)*128 + col0 + nn];
        }
        __syncthreads();
        #pragma unroll
        for(int kk=0;kk<16;kk++){
            float a[4], b[4];
            #pragma unroll
            for(int i=0;i<4;i++) a[i] = As[kk][ty*4+i];
            #pragma unroll
            for(int j=0;j<4;j++) b[j] = Bs[kk][tx*4+j];
            #pragma unroll
            for(int i=0;i<4;i++)
                #pragma unroll
                for(int j=0;j<4;j++) acc[i][j] += a[i]*b[j];
        }
        __syncthreads();
    }
    #pragma unroll
    for(int i=0;i<4;i++){
        int r = row0 + ty*4 + i;
        #pragma unroll
        for(int j=0;j<4;j++){
            int o = col0 + tx*4 + j;
            g_a1[(size_t)r*128 + o] = acc[i][j] + bias[o];
        }
    }
}

// ---------------- c2: K=7 pad=3, 128 -> 128 ----------------
__global__ void k_gemm_c2(const float* __restrict__ bias){
    __shared__ float As[16][65];
    __shared__ float Bs[16][65];
    __shared__ int lrow[64];
    int row0 = blockIdx.x*64;
    int col0 = blockIdx.y*64;
    int tid = threadIdx.x;
    int tx = tid & 15, ty = tid >> 4;
    if(tid < 64) lrow[tid] = (row0 + tid) % LL;
    __syncthreads();
    float acc[4][4] = {};
    for(int k7=0;k7<7;k7++){
        int dl = k7 - 3;
        for(int c0=0;c0<128;c0+=16){
            #pragma unroll
            for(int rep=0;rep<4;rep++){
                int lin = tid + rep*256;
                int kk = lin & 15, m = lin >> 4;
                int l2 = lrow[m] + dl;
                float v = 0.f;
                if(l2 >= 0 && l2 < LL)
                    v = g_a1[(size_t)(row0 + m + dl)*128 + c0 + kk];
                As[kk][m] = v;
            }
            #pragma unroll
            for(int rep=0;rep<4;rep++){
                int lin = tid + rep*256;
                int nn = lin & 63, kk = lin >> 6;
                Bs[kk][nn] = g_w2t[(k7*128 + c0 + kk)*128 + col0 + nn];
            }
            __syncthreads();
            #pragma unroll
            for(int kk=0;kk<16;kk++){
                float a[4], b[4];
                #pragma unroll
                for(int i=0;i<4;i++) a[i] = As[kk][ty*4+i];
                #pragma unroll
                for(int j=0;j<4;j++) b[j] = Bs[kk][tx*4+j];
                #pragma unroll
                for(int i=0;i<4;i++)
                    #pragma unroll
                    for(int j=0;j<4;j++) acc[i][j] += a[i]*b[j];
            }
            __syncthreads();
        }
    }
    #pragma unroll
    for(int i=0;i<4;i++){
        int r = row0 + ty*4 + i;
        #pragma unroll
        for(int j=0;j<4;j++){
            int o = col0 + tx*4 + j;
            g_a2[(size_t)r*128 + o] = acc[i][j] + bias[o];
        }
    }
}

// ---------------- c3: 1x1, 128 -> 64 ----------------
__global__ void k_gemm_c3(const float* __restrict__ bias){
    __shared__ float As[16][65];
    __shared__ float Bs[16][65];
    int row0 = blockIdx.x*64;
    int tid = threadIdx.x;
    int tx = tid & 15, ty = tid >> 4;
    float acc[4][4] = {};
    for(int c0=0;c0<128;c0+=16){
        #pragma unroll
        for(int rep=0;rep<4;rep++){
            int lin = tid + rep*256;
            int kk = lin & 15, m = lin >> 4;
            As[kk][m] = g_a2[(size_t)(row0+m)*128 + c0 + kk];
        }
        #pragma unroll
        for(int rep=0;rep<4;rep++){
            int lin = tid + rep*256;
            int nn = lin & 63, kk = lin >> 6;
            Bs[kk][nn] = g_w3t[(c0+kk)*64 + nn];
        }
        __syncthreads();
        #pragma unroll
        for(int kk=0;kk<16;kk++){
            float a[4], b[4];
            #pragma unroll
            for(int i=0;i<4;i++) a[i] = As[kk][ty*4+i];
            #pragma unroll
            for(int j=0;j<4;j++) b[j] = Bs[kk][tx*4+j];
            #pragma unroll
            for(int i=0;i<4;i++)
                #pragma unroll
                for(int j=0;j<4;j++) acc[i][j] += a[i]*b[j];
        }
        __syncthreads();
    }
    #pragma unroll
    for(int i=0;i<4;i++){
        int r = row0 + ty*4 + i;
        #pragma unroll
        for(int j=0;j<4;j++){
            int o = tx*4 + j;
            g_a3r[(size_t)r*64 + o] = acc[i][j] + bias[o];
        }
    }
}

// ---------------- per-sample layernorm stats (gn1/gn2/gn3) ----------------
__global__ void k_stats(int which){
    const float* buf = (which==0) ? g_a1 : (which==1) ? g_a2 : g_a3r;
    int chn = (which==2) ? 64 : 128;
    int n = blockIdx.x;
    int len = LL*chn;
    size_t base = (size_t)n * len;
    double s=0.0, q=0.0;
    for(int i=threadIdx.x;i<len;i+=256){ double v = buf[base+i]; s += v; q += v*v; }
    __shared__ double shs[256], shq[256];
    int tid = threadIdx.x;
    shs[tid]=s; shq[tid]=q; __syncthreads();
    for(int o=128;o>0;o>>=1){ if(tid<o){shs[tid]+=shs[tid+o]; shq[tid]+=shq[tid+o];} __syncthreads(); }
    if(tid==0){
        double m = shs[0]/len;
        double v = shq[0]/len - m*m;
        g_stats[which][n*2]   = (float)m;
        g_stats[which][n*2+1] = rsqrtf((float)v + EPSV);
    }
}

// ---------------- norm + prelu (in place, gn1/gn2) ----------------
__global__ void k_apply(int which, const float* __restrict__ w, const float* __restrict__ b){
    float* buf = (which==0) ? g_a1 : g_a2;
    const int chn = 128;
    const int per = LL*chn;
    int total = F*per;
    for(int i = blockIdx.x*blockDim.x + threadIdx.x; i < total; i += gridDim.x*blockDim.x){
        int c = i % chn;
        int n = i / per;
        float m = g_stats[which][n*2], rs = g_stats[which][n*2+1];
        float v = (buf[i]-m)*rs*w[c] + b[c];
        buf[i] = (v >= 0.f) ? v : 0.25f*v;
    }
}

// ---------------- gn3 + prelu + skip (s2) ----------------
__global__ void k_apply3(const float* __restrict__ w, const float* __restrict__ b){
    const int chn = 64;
    const int per = LL*chn;
    int total = F*per;
    for(int i = blockIdx.x*blockDim.x + threadIdx.x; i < total; i += gridDim.x*blockDim.x){
        int c = i % chn;
        int n = i / per;
        float m = g_stats[2][n*2], rs = g_stats[2][n*2+1];
        float v = (g_a3r[i]-m)*rs*w[c] + b[c];
        v = (v >= 0.f) ? v : 0.25f*v;
        g_a3[i] = v + g_y[i];
    }
}

// ---------------- transposed conv ct + residual skip + final layout ----------------
// out[(o*256+n)*512+p] = sum_{j,c} a3[n][p-j][c]*wct[j][c][o] + ct_b[o] + x[(o*256+n)*512+p]
__global__ void k_gemm_ct(const float* __restrict__ bias, const float* __restrict__ x,
                          float* __restrict__ out){
    __shared__ float As[16][65];
    __shared__ float Bs[16][65];
    __shared__ int arow[64];
    __shared__ int prow[64];
    int row0 = blockIdx.x*64;
    int tid = threadIdx.x;
    int tx = tid & 15, ty = tid >> 4;
    if(tid < 64){
        int r = row0 + tid;
        int n = r >> 9; int p = r & 511;
        arow[tid] = n*LL + p;
        prow[tid] = p;
    }
    __syncthreads();
    float acc[4][4] = {};
    for(int j7=0;j7<7;j7++){
        for(int c0=0;c0<64;c0+=16){
            #pragma unroll
            for(int rep=0;rep<4;rep++){
                int lin = tid + rep*256;
                int kk = lin & 15, m = lin >> 4;
                int l2 = prow[m] - j7;
                float v = 0.f;
                if(l2 >= 0 && l2 < LL)
                    v = g_a3[(size_t)(arow[m] - j7)*64 + c0 + kk];
                As[kk][m] = v;
            }
            #pragma unroll
            for(int rep=0;rep<4;rep++){
                int lin = tid + rep*256;
                int nn = lin & 63, kk = lin >> 6;
                Bs[kk][nn] = g_wct[(j7*64 + c0 + kk)*64 + nn];
            }
            __syncthreads();
            #pragma unroll
            for(int kk=0;kk<16;kk++){
                float a[4], b[4];
                #pragma unroll
                for(int i=0;i<4;i++) a[i] = As[kk][ty*4+i];
                #pragma unroll
                for(int j=0;j<4;j++) b[j] = Bs[kk][tx*4+j];
                #pragma unroll
                for(int i=0;i<4;i++)
                    #pragma unroll
                    for(int j=0;j<4;j++) acc[i][j] += a[i]*b[j];
            }
            __syncthreads();
        }
    }
    #pragma unroll
    for(int i=0;i<4;i++){
        int r = row0 + ty*4 + i;
        int n = r >> 9; int p = r & 511;
        #pragma unroll
        for(int j=0;j<4;j++){
            int o = tx*4 + j;
            size_t idx = ((size_t)o*F + n)*T + p;
            out[idx] = acc[i][j] + bias[o] + x[idx];
        }
    }
}

// ---------------- launcher ----------------
extern "C" void kernel_launch(void* const* d_in, const int* in_sizes, int n_in,
                              void* d_out, int out_size){
    const float* x    = (const float*)d_in[0];
    const float* gn0w = (const float*)d_in[1];
    const float* gn0b = (const float*)d_in[2];
    const float* sruw = (const float*)d_in[3];
    const float* sruv = (const float*)d_in[4];
    const float* srub = (const float*)d_in[5];
    const float* c1w  = (const float*)d_in[6];
    const float* c1b  = (const float*)d_in[7];
    const float* gn1w = (const float*)d_in[8];
    const float* gn1b = (const float*)d_in[9];
    const float* c2w  = (const float*)d_in[10];
    const float* c2b  = (const float*)d_in[11];
    const float* gn2w = (const float*)d_in[12];
    const float* gn2b = (const float*)d_in[13];
    const float* c3w  = (const float*)d_in[14];
    const float* c3b  = (const float*)d_in[15];
    const float* gn3w = (const float*)d_in[16];
    const float* gn3b = (const float*)d_in[17];
    const float* ctw  = (const float*)d_in[18];
    const float* ctb  = (const float*)d_in[19];
    float* out = (float*)d_out;

    k_red0 <<<512,256>>>(x);
    k_red0b<<<1,256>>>();
    k_prep <<<624,256>>>(c1w, c2w, c3w, ctw);
    k_xn   <<<dim3(16,256),256>>>(x, gn0w, gn0b);
    k_gemm_sru<<<dim3(M_ROWS/64,4),256>>>(sruw);
    k_scan <<<128,128>>>(sruv, srub);
    k_gemm_c1<<<dim3(M_ROWS/64,2),256>>>(c1b);
    k_stats<<<F,256>>>(0);
    k_apply<<<4096,256>>>(0, gn1w, gn1b);
    k_gemm_c2<<<dim3(M_ROWS/64,2),256>>>(c2b);
    k_stats<<<F,256>>>(1);
    k_apply<<<4096,256>>>(1, gn2w, gn2b);
    k_gemm_c3<<<dim3(M_ROWS/64,1),256>>>(c3b);
    k_stats<<<F,256>>>(2);
    k_apply3<<<2048,256>>>(gn3w, gn3b);
    k_gemm_ct<<<dim3((F*T)/64,1),256>>>(ctb, x, out);
}

// round 4
// speedup vs baseline: 1.7715x; 1.7715x over previous
#include <cuda_runtime.h>
#include <cuda_bf16.h>
#include <math.h>
#include <stdint.h>

// Problem constants
#define C0 64
#define T  512
#define F  256
#define LL 506
#define KW 7
#define C2 128
#define M_ROWS (F*LL)          // 129536
#define U_STRIDE (M_ROWS*128)  // 16580608
#define EPSV 1e-6f

// ---------------- scratch ----------------
__device__ float  g_X2 [T*F*C0];
__device__ float  g_U  [2*M_ROWS*128];
__device__ float  g_y  [M_ROWS*C0];
__device__ float  g_a1 [M_ROWS*C2];
__device__ float  g_a2 [M_ROWS*C2];
__device__ float  g_a3r[M_ROWS*C0];
__device__ float  g_a3 [M_ROWS*C0];
__device__ double g_part[1024];
__device__ float  g_stats0[2];
__device__ float  g_stats[3][F*2];
// tf32 hi/lo split, K-major weights: [o][k]
__device__ float  g_wsruh[256*448], g_wsrul[256*448];
__device__ float  g_w2h [128*896],  g_w2l [128*896];
__device__ float  g_w1h [128*64],   g_w1l [128*64];
__device__ float  g_w3h [64*128],   g_w3l [64*128];
__device__ float  g_wcth[64*448],   g_wctl[64*448];

__device__ __forceinline__ float sigf(float v){ return 1.f/(1.f+__expf(-v)); }
__device__ __forceinline__ uint32_t tf32b(float f){
    uint32_t u; asm("cvt.rna.tf32.f32 %0, %1;" : "=r"(u) : "f"(f)); return u;
}
__device__ __forceinline__ float tf32f(float f){ return __uint_as_float(tf32b(f)); }

// ---------------- gn0 reductions ----------------
__global__ void k_red0(const float* __restrict__ x){
    double s=0.0, q=0.0;
    for(int i = blockIdx.x*256 + threadIdx.x; i < T*F*C0; i += 512*256){
        double v = x[i]; s += v; q += v*v;
    }
    __shared__ double shs[256], shq[256];
    int tid = threadIdx.x;
    shs[tid]=s; shq[tid]=q; __syncthreads();
    for(int o=128;o>0;o>>=1){ if(tid<o){shs[tid]+=shs[tid+o]; shq[tid]+=shq[tid+o];} __syncthreads(); }
    if(tid==0){ g_part[blockIdx.x*2]=shs[0]; g_part[blockIdx.x*2+1]=shq[0]; }
}
__global__ void k_red0b(){
    double s=0.0, q=0.0;
    int tid = threadIdx.x;
    for(int b=tid;b<512;b+=256){ s += g_part[2*b]; q += g_part[2*b+1]; }
    __shared__ double shs[256], shq[256];
    shs[tid]=s; shq[tid]=q; __syncthreads();
    for(int o=128;o>0;o>>=1){ if(tid<o){shs[tid]+=shs[tid+o]; shq[tid]+=shq[tid+o];} __syncthreads(); }
    if(tid==0){
        double n = (double)T*F*C0;
        double m = shs[0]/n;
        double v = shq[0]/n - m*m;
        g_stats0[0] = (float)m;
        g_stats0[1] = rsqrtf((float)v + EPSV);
    }
}

// ---------------- weight prep: K-major [o][k], tf32 hi/lo split ----------------
__global__ void k_prep(const float* __restrict__ w1, const float* __restrict__ w2,
                       const float* __restrict__ w3, const float* __restrict__ wc,
                       const float* __restrict__ sw){
    int i = blockIdx.x*blockDim.x + threadIdx.x;
    if(i < 114688){
        int o=i/448, kl=i%448, k7=kl>>6, c=kl&63;
        float v = sw[(o>>7)*57344 + (c*7+k7)*128 + (o&127)];
        float h = tf32f(v); g_wsruh[i]=h; g_wsrul[i]=tf32f(v-h); return;
    }
    i -= 114688;
    if(i < 114688){
        int o=i/896, kl=i%896, k7=kl>>7, c=kl&127;
        float v = w2[o*896 + c*7 + k7];
        float h = tf32f(v); g_w2h[i]=h; g_w2l[i]=tf32f(v-h); return;
    }
    i -= 114688;
    if(i < 8192){ float v=w1[i]; float h=tf32f(v); g_w1h[i]=h; g_w1l[i]=tf32f(v-h); return; }
    i -= 8192;
    if(i < 8192){ float v=w3[i]; float h=tf32f(v); g_w3h[i]=h; g_w3l[i]=tf32f(v-h); return; }
    i -= 8192;
    if(i < 28672){
        int o=i/448, kl=i%448, k7=kl>>6, c=kl&63;
        float v = wc[c*448 + o*7 + k7];
        float h = tf32f(v); g_wcth[i]=h; g_wctl[i]=tf32f(v-h);
    }
}

// ---------------- gn0 apply + transpose to [t][f][c] ----------------
__global__ void k_xn(const float* __restrict__ x, const float* __restrict__ w, const float* __restrict__ b){
    __shared__ float sm[32*65];
    int t0 = blockIdx.x*32;
    int f  = blockIdx.y;
    int tid = threadIdx.x;
    float mean = g_stats0[0], rstd = g_stats0[1];
    #pragma unroll
    for(int rep=0;rep<8;rep++){
        int lin = tid + rep*256;
        int c = lin >> 5, tl = lin & 31;
        float v = x[((size_t)c*F + f)*T + t0 + tl];
        v = (v-mean)*rstd*w[c] + b[c];
        sm[tl*65 + c] = v;
    }
    __syncthreads();
    #pragma unroll
    for(int rep=0;rep<8;rep++){
        int lin = tid + rep*256;
        int c = lin & 63, tl = lin >> 6;
        g_X2[((size_t)(t0+tl)*F + f)*C0 + c] = sm[tl*65 + c];
    }
}

// ---------------- tf32x3 mma.sync GEMM (block 128x64, 8 warps, warp 32x32) ----------------
enum { M_SRU=0, M_C1=1, M_C2=2, M_C3=3, M_CT=4 };

__device__ __forceinline__ void mma8(float* c, const uint32_t* a, const uint32_t* b){
    asm volatile(
        "mma.sync.aligned.m16n8k8.row.col.f32.tf32.tf32.f32 "
        "{%0,%1,%2,%3},{%4,%5,%6,%7},{%8,%9},{%0,%1,%2,%3};"
        : "+f"(c[0]), "+f"(c[1]), "+f"(c[2]), "+f"(c[3])
        : "r"(a[0]), "r"(a[1]), "r"(a[2]), "r"(a[3]), "r"(b[0]), "r"(b[1]));
}

#define SMEM_FLOATS (128*36*2 + 64*36*2)   // 13824 floats = 55296 B

template<int MODE, int KCHUNKS, int KTOT>
__global__ void __launch_bounds__(256)
k_mma(const float* __restrict__ bias, const float* __restrict__ xs, float* __restrict__ outp){
    extern __shared__ float dsm[];
    float* AsH = dsm;               // [128][36]
    float* AsL = AsH + 128*36;
    float* BsH = AsL + 128*36;      // [64][36]
    float* BsL = BsH + 64*36;
    __shared__ int s_aux[128];

    const int tid = threadIdx.x, lane = tid & 31, wid = tid >> 5;
    const int warp_m = wid & 3, warp_n = wid >> 2;
    const int lr = lane >> 2, lc = lane & 3;
    const int col0 = blockIdx.x * 64;
    const int row0 = blockIdx.y * 128;

    const float* Ap  = (MODE==M_SRU)? g_X2   : (MODE==M_C1)? g_y   : (MODE==M_C2)? g_a1 : (MODE==M_C3)? g_a2 : g_a3;
    const float* BpH = (MODE==M_SRU)? g_wsruh: (MODE==M_C1)? g_w1h : (MODE==M_C2)? g_w2h: (MODE==M_C3)? g_w3h: g_wcth;
    const float* BpL = (MODE==M_SRU)? g_wsrul: (MODE==M_C1)? g_w1l : (MODE==M_C2)? g_w2l: (MODE==M_C3)? g_w3l: g_wctl;

    if(MODE==M_C2 || MODE==M_CT){
        if(tid<128){
            int r = row0 + tid;
            s_aux[tid] = (MODE==M_C2) ? (r % LL) : (r & 511);
        }
        __syncthreads();
    }

    float acc[2][4][4] = {};

    for(int ch=0; ch<KCHUNKS; ch++){
        int k7, c0;
        if(MODE==M_SRU || MODE==M_CT){ k7 = ch>>1; c0 = (ch&1)*32; }
        else if(MODE==M_C2){ k7 = ch>>2; c0 = (ch&3)*32; }
        else { k7 = 0; c0 = ch*32; }
        const int kbase = ch*32;

        // ---- gather A (128x32) and B hi/lo (64x32) ----
        float4 av[4];
        #pragma unroll
        for(int rep=0;rep<4;rep++){
            int lin = tid + rep*256;
            int m = lin>>3, c4 = lin&7;
            float4 v = make_float4(0.f,0.f,0.f,0.f);
            if(MODE==M_SRU){
                v = *(const float4*)(Ap + (size_t)(row0+m+k7*256)*64 + c0 + c4*4);
            } else if(MODE==M_C1){
                v = *(const float4*)(Ap + (size_t)(row0+m)*64 + c0 + c4*4);
            } else if(MODE==M_C2){
                int l2 = s_aux[m] + k7 - 3;
                if((unsigned)l2 < LL)
                    v = *(const float4*)(Ap + (size_t)(row0+m+k7-3)*128 + c0 + c4*4);
            } else if(MODE==M_C3){
                v = *(const float4*)(Ap + (size_t)(row0+m)*128 + c0 + c4*4);
            } else {
                int p2 = s_aux[m] - k7;
                if((unsigned)p2 < LL){
                    int n = (row0+m)>>9;
                    v = *(const float4*)(Ap + ((size_t)n*LL + p2)*64 + c0 + c4*4);
                }
            }
            av[rep] = v;
        }
        float4 bvh[2], bvl[2];
        #pragma unroll
        for(int rep=0;rep<2;rep++){
            int lin = tid + rep*256;
            int o = lin>>3, c4 = lin&7;
            bvh[rep] = *(const float4*)(BpH + (size_t)(col0+o)*KTOT + kbase + c4*4);
            bvl[rep] = *(const float4*)(BpL + (size_t)(col0+o)*KTOT + kbase + c4*4);
        }
        if(ch) __syncthreads();
        #pragma unroll
        for(int rep=0;rep<4;rep++){
            int lin = tid + rep*256;
            int m = lin>>3, c4 = lin&7;
            float h0=tf32f(av[rep].x), h1=tf32f(av[rep].y), h2=tf32f(av[rep].z), h3=tf32f(av[rep].w);
            AsH[m*36+c4*4+0]=h0; AsL[m*36+c4*4+0]=tf32f(av[rep].x-h0);
            AsH[m*36+c4*4+1]=h1; AsL[m*36+c4*4+1]=tf32f(av[rep].y-h1);
            AsH[m*36+c4*4+2]=h2; AsL[m*36+c4*4+2]=tf32f(av[rep].z-h2);
            AsH[m*36+c4*4+3]=h3; AsL[m*36+c4*4+3]=tf32f(av[rep].w-h3);
        }
        #pragma unroll
        for(int rep=0;rep<2;rep++){
            int lin = tid + rep*256;
            int o = lin>>3, c4 = lin&7;
            *(float4*)&BsH[o*36+c4*4] = bvh[rep];
            *(float4*)&BsL[o*36+c4*4] = bvl[rep];
        }
        __syncthreads();

        // ---- 4 k8 steps, 3 mma per fragment pair (hh, hl, lh) ----
        #pragma unroll
        for(int k8=0;k8<4;k8++){
            const int kk = k8*8;
            uint32_t ah[2][4], al[2][4];
            #pragma unroll
            for(int mi=0;mi<2;mi++){
                int rm = (warp_m*32 + mi*16)*36;
                ah[mi][0] = __float_as_uint(AsH[rm + lr*36      + kk+lc  ]);
                ah[mi][1] = __float_as_uint(AsH[rm + (lr+8)*36  + kk+lc  ]);
                ah[mi][2] = __float_as_uint(AsH[rm + lr*36      + kk+lc+4]);
                ah[mi][3] = __float_as_uint(AsH[rm + (lr+8)*36  + kk+lc+4]);
                al[mi][0] = __float_as_uint(AsL[rm + lr*36      + kk+lc  ]);
                al[mi][1] = __float_as_uint(AsL[rm + (lr+8)*36  + kk+lc  ]);
                al[mi][2] = __float_as_uint(AsL[rm + lr*36      + kk+lc+4]);
                al[mi][3] = __float_as_uint(AsL[rm + (lr+8)*36  + kk+lc+4]);
            }
            #pragma unroll
            for(int ni=0;ni<4;ni++){
                int nb = (warp_n*32 + ni*8 + lr)*36;
                uint32_t bh[2], bl[2];
                bh[0] = __float_as_uint(BsH[nb + kk+lc  ]);
                bh[1] = __float_as_uint(BsH[nb + kk+lc+4]);
                bl[0] = __float_as_uint(BsL[nb + kk+lc  ]);
                bl[1] = __float_as_uint(BsL[nb + kk+lc+4]);
                mma8(acc[0][ni], ah[0], bh);
                mma8(acc[0][ni], al[0], bh);
                mma8(acc[0][ni], ah[0], bl);
                mma8(acc[1][ni], ah[1], bh);
                mma8(acc[1][ni], al[1], bh);
                mma8(acc[1][ni], ah[1], bl);
            }
        }
    }

    // ---- staged epilogue: smem C tile then coalesced global store ----
    __syncthreads();
    float* Cs = dsm;   // [128][65]
    #pragma unroll
    for(int mi=0;mi<2;mi++){
        int rl = warp_m*32 + mi*16 + lr;
        #pragma unroll
        for(int ni=0;ni<4;ni++){
            int cl = warp_n*32 + ni*8 + 2*lc;
            #pragma unroll
            for(int rr=0;rr<2;rr++){
                Cs[(rl+rr*8)*65 + cl]   = acc[mi][ni][rr*2];
                Cs[(rl+rr*8)*65 + cl+1] = acc[mi][ni][rr*2+1];
            }
        }
    }
    __syncthreads();

    if(MODE==M_CT){
        int n = row0 >> 9, p0 = row0 & 511;
        #pragma unroll 4
        for(int i=tid;i<64*128;i+=256){
            int o = i>>7, m = i&127;
            size_t idx = ((size_t)o*F + n)*T + p0 + m;
            outp[idx] = Cs[m*65+o] + bias[o] + xs[idx];
        }
    } else if(MODE==M_SRU){
        int d = col0>>7, cb = col0 & 127;
        #pragma unroll 4
        for(int i=tid;i<128*64;i+=256){
            int m = i>>6, o = i&63;
            g_U[(size_t)d*U_STRIDE + (size_t)(row0+m)*128 + cb + o] = Cs[m*65+o];
        }
    } else {
        float* dst = (MODE==M_C1)? g_a1 : (MODE==M_C2)? g_a2 : g_a3r;
        const int stride = (MODE==M_C3)? 64 : 128;
        #pragma unroll 4
        for(int i=tid;i<128*64;i+=256){
            int m = i>>6, o = i&63;
            dst[(size_t)(row0+m)*stride + col0 + o] = Cs[m*65+o] + bias[col0+o];
        }
    }
}

// ---------------- SRU scan (1-step prefetch) ----------------
__global__ void k_scan(const float* __restrict__ sruv, const float* __restrict__ srub){
    int w = (blockIdx.x*blockDim.x + threadIdx.x) >> 5;
    int h = threadIdx.x & 31;
    int d = w >> 8; int n = w & 255;
    float vf = sruv[d*64 + h];
    float vr = sruv[d*64 + 32 + h];
    float bf = srub[d*64 + h];
    float br = srub[d*64 + 32 + h];
    float st = 0.f;
    const float* Ubase = g_U + (size_t)d*U_STRIDE + (size_t)n*128;
    int l = d ? (LL-1) : 0;
    const float* u = Ubase + (size_t)l*(256*128);
    float u0=u[h], u1=u[32+h], u2=u[64+h], u3=u[96+h];
    for(int s=0;s<LL;s++){
        float n0=0,n1=0,n2=0,n3=0;
        int ln = 0;
        if(s+1 < LL){
            ln = d ? (LL-2-s) : (s+1);
            const float* un = Ubase + (size_t)ln*(256*128);
            n0=un[h]; n1=un[32+h]; n2=un[64+h]; n3=un[96+h];
        }
        float f  = sigf(u1 + vf*st + bf);
        float cn = f*st + (1.f-f)*u0;
        float rr = sigf(u2 + vr*st + br);
        float hv = rr*cn + (1.f-rr)*u3;
        st = cn;
        g_y[((size_t)n*LL + l)*64 + d*32 + h] = hv;
        l = ln; u0=n0; u1=n1; u2=n2; u3=n3;
    }
}

// ---------------- per-sample layernorm stats ----------------
__global__ void k_stats(int which){
    const float* buf = (which==0) ? g_a1 : (which==1) ? g_a2 : g_a3r;
    int chn = (which==2) ? 64 : 128;
    int n = blockIdx.x;
    int len = LL*chn;
    size_t base = (size_t)n * len;
    double s=0.0, q=0.0;
    for(int i=threadIdx.x;i<len;i+=256){ double v = buf[base+i]; s += v; q += v*v; }
    __shared__ double shs[256], shq[256];
    int tid = threadIdx.x;
    shs[tid]=s; shq[tid]=q; __syncthreads();
    for(int o=128;o>0;o>>=1){ if(tid<o){shs[tid]+=shs[tid+o]; shq[tid]+=shq[tid+o];} __syncthreads(); }
    if(tid==0){
        double m = shs[0]/len;
        double v = shq[0]/len - m*m;
        g_stats[which][n*2]   = (float)m;
        g_stats[which][n*2+1] = rsqrtf((float)v + EPSV);
    }
}

__global__ void k_apply(int which, const float* __restrict__ w, const float* __restrict__ b){
    float* buf = (which==0) ? g_a1 : g_a2;
    const int chn = 128;
    const int per = LL*chn;
    int total = F*per;
    for(int i = blockIdx.x*blockDim.x + threadIdx.x; i < total; i += gridDim.x*blockDim.x){
        int c = i % chn;
        int n = i / per;
        float m = g_stats[which][n*2], rs = g_stats[which][n*2+1];
        float v = (buf[i]-m)*rs*w[c] + b[c];
        buf[i] = (v >= 0.f) ? v : 0.25f*v;
    }
}

__global__ void k_apply3(const float* __restrict__ w, const float* __restrict__ b){
    const int chn = 64;
    const int per = LL*chn;
    int total = F*per;
    for(int i = blockIdx.x*blockDim.x + threadIdx.x; i < total; i += gridDim.x*blockDim.x){
        int c = i % chn;
        int n = i / per;
        float m = g_stats[2][n*2], rs = g_stats[2][n*2+1];
        float v = (g_a3r[i]-m)*rs*w[c] + b[c];
        v = (v >= 0.f) ? v : 0.25f*v;
        g_a3[i] = v + g_y[i];
    }
}

// ---------------- launcher ----------------
extern "C" void kernel_launch(void* const* d_in, const int* in_sizes, int n_in,
                              void* d_out, int out_size){
    const float* x    = (const float*)d_in[0];
    const float* gn0w = (const float*)d_in[1];
    const float* gn0b = (const float*)d_in[2];
    const float* sruw = (const float*)d_in[3];
    const float* sruv = (const float*)d_in[4];
    const float* srub = (const float*)d_in[5];
    const float* c1w  = (const float*)d_in[6];
    const float* c1b  = (const float*)d_in[7];
    const float* gn1w = (const float*)d_in[8];
    const float* gn1b = (const float*)d_in[9];
    const float* c2w  = (const float*)d_in[10];
    const float* c2b  = (const float*)d_in[11];
    const float* gn2w = (const float*)d_in[12];
    const float* gn2b = (const float*)d_in[13];
    const float* c3w  = (const float*)d_in[14];
    const float* c3b  = (const float*)d_in[15];
    const float* gn3w = (const float*)d_in[16];
    const float* gn3b = (const float*)d_in[17];
    const float* ctw  = (const float*)d_in[18];
    const float* ctb  = (const float*)d_in[19];
    float* out = (float*)d_out;

    const int smem = SMEM_FLOATS*4;   // 55296 B
    cudaFuncSetAttribute(k_mma<M_SRU,14,448>, cudaFuncAttributeMaxDynamicSharedMemorySize, smem);
    cudaFuncSetAttribute(k_mma<M_C1 , 2, 64>, cudaFuncAttributeMaxDynamicSharedMemorySize, smem);
    cudaFuncSetAttribute(k_mma<M_C2 ,28,896>, cudaFuncAttributeMaxDynamicSharedMemorySize, smem);
    cudaFuncSetAttribute(k_mma<M_C3 , 4,128>, cudaFuncAttributeMaxDynamicSharedMemorySize, smem);
    cudaFuncSetAttribute(k_mma<M_CT ,14,448>, cudaFuncAttributeMaxDynamicSharedMemorySize, smem);

    k_red0 <<<512,256>>>(x);
    k_red0b<<<1,256>>>();
    k_prep <<<1072,256>>>(c1w, c2w, c3w, ctw, sruw);
    k_xn   <<<dim3(16,256),256>>>(x, gn0w, gn0b);

    k_mma<M_SRU,14,448><<<dim3(4,M_ROWS/128),256,smem>>>(nullptr, nullptr, nullptr);
    k_scan <<<128,128>>>(sruv, srub);

    k_mma<M_C1,2,64>  <<<dim3(2,M_ROWS/128),256,smem>>>(c1b, nullptr, nullptr);
    k_stats<<<F,256>>>(0);
    k_apply<<<4096,256>>>(0, gn1w, gn1b);

    k_mma<M_C2,28,896><<<dim3(2,M_ROWS/128),256,smem>>>(c2b, nullptr, nullptr);
    k_stats<<<F,256>>>(1);
    k_apply<<<4096,256>>>(1, gn2w, gn2b);

    k_mma<M_C3,4,128> <<<dim3(1,M_ROWS/128),256,smem>>>(c3b, nullptr, nullptr);
    k_stats<<<F,256>>>(2);
    k_apply3<<<2048,256>>>(gn3w, gn3b);

    k_mma<M_CT,14,448><<<dim3(1,(F*T)/128),256,smem>>>(ctb, x, out);
}